// round 11
// baseline (speedup 1.0000x reference)
#include <cuda_runtime.h>
#include <cuda_fp16.h>
#include <cstdint>

#define BQ    8
#define CINC  128
#define COUTC 128
#define HH    256
#define WW    256
#define HEADS 32
#define HWSZ  (HH * WW)        /* 65536 */
#define TOT   (BQ * HWSZ)      /* 524288 */
#define NPAIRS (TOT / 256)     /* 2048 */
#define GRID_FUSED 1024        /* 2 pairs per CTA, 7 CTA-waves x 2 = 14 slots */

// Scratch globals (allocation-free rule).
// g_value_h: fp16 value, [((b*32+head)*HW + hw)*2 + (ci>>1)] -> f16x2 per 2 ch
// g_flow:    [n2 * TOT + b*HW + hw]
__device__ __align__(16) uint32_t g_value_h[(size_t)TOT * HEADS * 2];
__device__ __align__(16) float g_flow[(size_t)(2 * HEADS) * TOT];

// Pre-packed fp16 weight fragments, m16n8k16 B-operand order, hi/lo fused:
// slot (nt*8 + kt)*32 + lane -> uint4 {hi_b0, hi_b1, lo_b0, lo_b1}
__device__ __align__(16) uint4 g_wv_p[4096];   // 16 ntiles
__device__ __align__(16) uint4 g_wf1_p[4096];  // 16 ntiles
__device__ __align__(16) uint4 g_wf2_p[2048];  // 8 ntiles

// ---------------------------------------------------------------------------
// helpers — fp16 hi/lo split (v ~= hi + lo, each packed f16x2, v0 -> low half)
// ---------------------------------------------------------------------------
__device__ __forceinline__ void split2(float v0, float v1, uint32_t& hi, uint32_t& lo) {
    asm("cvt.rn.f16x2.f32 %0, %1, %2;" : "=r"(hi) : "f"(v1), "f"(v0));
    float h0, h1;
    asm("{.reg .f16 x, y;\n\t mov.b32 {x, y}, %2;\n\t"
        "cvt.f32.f16 %0, x;\n\t cvt.f32.f16 %1, y;}"
        : "=f"(h0), "=f"(h1) : "r"(hi));
    const float r0 = v0 - h0;
    const float r1 = v1 - h1;
    asm("cvt.rn.f16x2.f32 %0, %1, %2;" : "=r"(lo) : "f"(r1), "f"(r0));
}
__device__ __forceinline__ uint32_t pack_h2(float v0, float v1) {
    uint32_t p;
    asm("cvt.rn.f16x2.f32 %0, %1, %2;" : "=r"(p) : "f"(v1), "f"(v0));
    return p;
}
__device__ __forceinline__ void mma16816(float* c, uint32_t a0, uint32_t a1,
                                         uint32_t a2, uint32_t a3,
                                         uint32_t b0, uint32_t b1) {
    asm volatile(
        "mma.sync.aligned.m16n8k16.row.col.f32.f16.f16.f32 "
        "{%0,%1,%2,%3}, {%4,%5,%6,%7}, {%8,%9}, {%0,%1,%2,%3};"
        : "+f"(c[0]), "+f"(c[1]), "+f"(c[2]), "+f"(c[3])
        : "r"(a0), "r"(a1), "r"(a2), "r"(a3), "r"(b0), "r"(b1));
}

// Prefetch one 128-pixel M-tile of u (512 x 128B lines) to L2. 512 thr x 1 line.
__device__ __forceinline__ void prefetch_tile(const float* __restrict__ uB, int t) {
    const float* p = uB + (size_t)(t >> 2) * HWSZ + (t & 3) * 32;
    asm volatile("prefetch.global.L2 [%0];" :: "l"(p));
}

// ---------------------------------------------------------------------------
// Kernel 0: pack weights into fp16 hi/lo fused B-fragments.
// ---------------------------------------------------------------------------
__global__ void split_weights(const float* __restrict__ wv,
                              const float* __restrict__ wf1,
                              const float* __restrict__ wf2) {
    const int idx  = blockIdx.x * 256 + threadIdx.x;  // 0..4095 (grid=16)
    const int lane = idx & 31;
    const int kt   = (idx >> 5) & 7;
    const int nt   = idx >> 8;          // 0..15
    const int n    = nt * 8 + (lane >> 2);
    const int k0   = kt * 16 + 2 * (lane & 3);

    {
        const float* W = wv + n * 128;
        uint4 P;
        split2(W[k0], W[k0 + 1], P.x, P.z);
        split2(W[k0 + 8], W[k0 + 9], P.y, P.w);
        g_wv_p[idx] = P;
    }
    {
        const float* W = wf1 + n * 128;
        uint4 P;
        split2(W[k0], W[k0 + 1], P.x, P.z);
        split2(W[k0 + 8], W[k0 + 9], P.y, P.w);
        g_wf1_p[idx] = P;
    }
    if (nt < 8) {
        const float* W = wf2 + n * 128;
        uint4 P;
        split2(W[k0], W[k0 + 1], P.x, P.z);
        split2(W[k0 + 8], W[k0 + 9], P.y, P.w);
        g_wf2_p[idx] = P;
    }
}

// ---------------------------------------------------------------------------
// Fused kernel v8: 512 threads (16 warps, warp grid 4m x 4n -> 4 warps/SMSP
// for HMMA latency hiding), grid 1024 with 2 pairs/CTA (tail = 14 slots,
// same as R10; B smem fill amortized 2x). Per 128-pixel tile: value+hmid
// GEMMs fused in one kt loop, then flow GEMM. fp16x3, fp32 accum, mma.sync.
// Value intermediate stored fp16. SMEM map as before (230KB, 1 CTA/SM).
// ---------------------------------------------------------------------------
#define SM_A_HI   0
#define SM_A_LO   32768
#define SM_BV     65536
#define SM_BF1    131072
#define SM_WF2    196608
#define SM_BIASF1 229376
#define SM_BIASF2 229888
#define SM_BIASV  230144
#define FUSED_SMEM 230656

__global__ __launch_bounds__(512, 1) void fused_gemm(const float* __restrict__ u,
                                                     const float* __restrict__ bf1,
                                                     const float* __restrict__ bf2,
                                                     const float* __restrict__ bv) {
    extern __shared__ char smem[];
    const int t    = threadIdx.x;
    const int wid  = t >> 5;    // 0..15
    const int lane = t & 31;
    const int wm   = wid & 3;   // m group (rows 32*wm)
    const int wn   = wid >> 2;  // n group 0..3

    // prefetch first pair's tile 0 to L2; B-copy below absorbs DRAM latency.
    {
        const int base0 = blockIdx.x * 256;
        const int b0    = base0 / HWSZ;
        prefetch_tile(u + (size_t)b0 * CINC * HWSZ + (base0 - b0 * HWSZ), t);
    }

    if (t < 128) ((float*)(smem + SM_BIASF1))[t] = bf1[t];
    if (t < 64)  ((float*)(smem + SM_BIASF2))[t] = bf2[t];
    if (t < 128) ((float*)(smem + SM_BIASV))[t]  = bv[t];

    // ---- 0. copy packed weight fragments to smem ONCE per CTA ----
    {
        uint4* dv = (uint4*)(smem + SM_BV);
        uint4* df = (uint4*)(smem + SM_BF1);
        uint4* d2 = (uint4*)(smem + SM_WF2);
#pragma unroll
        for (int i = t; i < 4096; i += 512) { dv[i] = g_wv_p[i]; df[i] = g_wf1_p[i]; }
#pragma unroll
        for (int i = t; i < 2048; i += 512) { d2[i] = g_wf2_p[i]; }
    }

    const float* bf1s = (const float*)(smem + SM_BIASF1);
    const float* bf2s = (const float*)(smem + SM_BIASF2);
    const float* bvs  = (const float*)(smem + SM_BIASV);

    for (int pair = blockIdx.x; pair < NPAIRS; pair += GRID_FUSED) {
        const int base0 = pair * 256;
        const int b     = base0 / HWSZ;       // same b for both tiles
        const float* uBb = u + (size_t)b * CINC * HWSZ;

        for (int sub = 0; sub < 2; ++sub) {
            const int m0  = base0 + sub * 128;
            const int hw0 = m0 - b * HWSZ;
            const float* uB = uBb + hw0;

            __syncthreads();  // prior GEMM2 A-reads (or B copy) complete

            // ---- 1. convert A tile -> hi/lo fragments directly from gmem ----
            // 16 warps: kt = wid&7, each half handles 4 mt values.
            {
                const int kt  = wid & 7;
                const int mtb = (wid >> 3) * 4;
                const int kk  = kt * 16 + 2 * (lane & 3);
                const float* p0 = uB + (size_t)kk * HWSZ;
                const float* p1 = uB + (size_t)(kk + 1) * HWSZ;
                const float* p2 = uB + (size_t)(kk + 8) * HWSZ;
                const float* p3 = uB + (size_t)(kk + 9) * HWSZ;
                uint4* AH = (uint4*)(smem + SM_A_HI);
                uint4* AL = (uint4*)(smem + SM_A_LO);
#pragma unroll
                for (int mi = 0; mi < 4; ++mi) {
                    const int mt = mtb + mi;
                    const int m  = mt * 16 + (lane >> 2);
                    const float f00 = p0[m],     f01 = p1[m];
                    const float f10 = p0[m + 8], f11 = p1[m + 8];
                    const float f20 = p2[m],     f21 = p3[m];
                    const float f30 = p2[m + 8], f31 = p3[m + 8];
                    uint4 H, L;
                    split2(f00, f01, H.x, L.x);
                    split2(f10, f11, H.y, L.y);
                    split2(f20, f21, H.z, L.z);
                    split2(f30, f31, H.w, L.w);
                    const int slot = (mt * 8 + kt) * 32 + lane;
                    AH[slot] = H;
                    AL[slot] = L;
                }
            }
            // prefetch next tile to L2 while this tile's GEMMs run.
            if (sub == 0) {
                prefetch_tile(uB + 128, t);
            } else {
                const int np = pair + GRID_FUSED;
                if (np < NPAIRS) {
                    const int nb0 = np * 256;
                    const int nb  = nb0 / HWSZ;
                    prefetch_tile(u + (size_t)nb * CINC * HWSZ + (nb0 - nb * HWSZ), t);
                }
            }
            __syncthreads();

            // ---- 2. value + hmid GEMMs fused (N=128 each), fp16x3 ----
            float cv[2][4][4];
            float ch[2][4][4];
#pragma unroll
            for (int i = 0; i < 2; ++i)
#pragma unroll
                for (int nt = 0; nt < 4; ++nt)
#pragma unroll
                    for (int r = 0; r < 4; ++r) { cv[i][nt][r] = 0.0f; ch[i][nt][r] = 0.0f; }

            {
                const uint4* AH = (const uint4*)(smem + SM_A_HI);
                const uint4* AL = (const uint4*)(smem + SM_A_LO);
                const uint4* BV = (const uint4*)(smem + SM_BV);
                const uint4* BF = (const uint4*)(smem + SM_BF1);
#pragma unroll
                for (int kt = 0; kt < 8; ++kt) {
                    const uint4 Ah0 = AH[((2 * wm + 0) * 8 + kt) * 32 + lane];
                    const uint4 Ah1 = AH[((2 * wm + 1) * 8 + kt) * 32 + lane];
                    const uint4 Al0 = AL[((2 * wm + 0) * 8 + kt) * 32 + lane];
                    const uint4 Al1 = AL[((2 * wm + 1) * 8 + kt) * 32 + lane];
#pragma unroll
                    for (int nt = 0; nt < 4; ++nt) {
                        const int bslot = ((4 * wn + nt) * 8 + kt) * 32 + lane;
                        const uint4 Bv = BV[bslot];
                        const uint4 Bf = BF[bslot];
                        mma16816(cv[0][nt], Ah0.x, Ah0.y, Ah0.z, Ah0.w, Bv.x, Bv.y);
                        mma16816(cv[1][nt], Ah1.x, Ah1.y, Ah1.z, Ah1.w, Bv.x, Bv.y);
                        mma16816(cv[0][nt], Ah0.x, Ah0.y, Ah0.z, Ah0.w, Bv.z, Bv.w);
                        mma16816(cv[1][nt], Ah1.x, Ah1.y, Ah1.z, Ah1.w, Bv.z, Bv.w);
                        mma16816(cv[0][nt], Al0.x, Al0.y, Al0.z, Al0.w, Bv.x, Bv.y);
                        mma16816(cv[1][nt], Al1.x, Al1.y, Al1.z, Al1.w, Bv.x, Bv.y);
                        mma16816(ch[0][nt], Ah0.x, Ah0.y, Ah0.z, Ah0.w, Bf.x, Bf.y);
                        mma16816(ch[1][nt], Ah1.x, Ah1.y, Ah1.z, Ah1.w, Bf.x, Bf.y);
                        mma16816(ch[0][nt], Ah0.x, Ah0.y, Ah0.z, Ah0.w, Bf.z, Bf.w);
                        mma16816(ch[1][nt], Ah1.x, Ah1.y, Ah1.z, Ah1.w, Bf.z, Bf.w);
                        mma16816(ch[0][nt], Al0.x, Al0.y, Al0.z, Al0.w, Bf.x, Bf.y);
                        mma16816(ch[1][nt], Al1.x, Al1.y, Al1.z, Al1.w, Bf.x, Bf.y);
                    }
                }
            }

            // ---- 3. value epilogue -> g_value_h (f16x2 per 2 channels) ----
            {
#pragma unroll
                for (int i = 0; i < 2; ++i) {
                    const int hwr = hw0 + 32 * wm + 16 * i + (lane >> 2);
#pragma unroll
                    for (int nt = 0; nt < 4; ++nt) {
                        const int n0   = 8 * (4 * wn + nt) + 2 * (lane & 3);
                        const int head = n0 >> 2;
                        const int cih  = (n0 & 3) >> 1;
                        const float bb0 = bvs[n0], bb1 = bvs[n0 + 1];
                        const size_t plane = ((size_t)b * HEADS + head) * HWSZ;
                        g_value_h[(plane + hwr) * 2 + cih] =
                            pack_h2(cv[i][nt][0] + bb0, cv[i][nt][1] + bb1);
                        g_value_h[(plane + hwr + 8) * 2 + cih] =
                            pack_h2(cv[i][nt][2] + bb0, cv[i][nt][3] + bb1);
                    }
                }
            }
            __syncthreads();  // all warps done reading A fragments

            // ---- 4. hmid -> relu -> fp16 split -> A2 fragments (reuse A) ----
            // Warp owns hmid cols [32wn, 32wn+32) = A2 kt tiles 2wn, 2wn+1.
            {
                uint4* AH = (uint4*)(smem + SM_A_HI);
                uint4* AL = (uint4*)(smem + SM_A_LO);
#pragma unroll
                for (int i = 0; i < 2; ++i) {
                    const int mtg = 2 * wm + i;
#pragma unroll
                    for (int kl = 0; kl < 2; ++kl) {
                        const int ktg = 2 * wn + kl;
                        const int nt0 = 2 * kl, nt1 = nt0 + 1;
                        const int n00 = 8 * (4 * wn + nt0) + 2 * (lane & 3);
                        const int n10 = n00 + 8;
                        const float b00 = bf1s[n00], b01 = bf1s[n00 + 1];
                        const float b10 = bf1s[n10], b11 = bf1s[n10 + 1];
                        uint4 H, L;
                        split2(fmaxf(ch[i][nt0][0] + b00, 0.0f),
                               fmaxf(ch[i][nt0][1] + b01, 0.0f), H.x, L.x);
                        split2(fmaxf(ch[i][nt0][2] + b00, 0.0f),
                               fmaxf(ch[i][nt0][3] + b01, 0.0f), H.y, L.y);
                        split2(fmaxf(ch[i][nt1][0] + b10, 0.0f),
                               fmaxf(ch[i][nt1][1] + b11, 0.0f), H.z, L.z);
                        split2(fmaxf(ch[i][nt1][2] + b10, 0.0f),
                               fmaxf(ch[i][nt1][3] + b11, 0.0f), H.w, L.w);
                        const int slot = (mtg * 8 + ktg) * 32 + lane;
                        AH[slot] = H;
                        AL[slot] = L;
                    }
                }
            }
            __syncthreads();

            // ---- 5. flow GEMM (N=64, warp tile 32x16) + epilogue ----
            {
                float cf[2][2][4];
#pragma unroll
                for (int i = 0; i < 2; ++i)
#pragma unroll
                    for (int j = 0; j < 2; ++j)
#pragma unroll
                        for (int r = 0; r < 4; ++r) cf[i][j][r] = 0.0f;

                const uint4* AH = (const uint4*)(smem + SM_A_HI);
                const uint4* AL = (const uint4*)(smem + SM_A_LO);
                const uint4* B2 = (const uint4*)(smem + SM_WF2);
#pragma unroll
                for (int kt = 0; kt < 8; ++kt) {
                    const uint4 Ah0 = AH[((2 * wm + 0) * 8 + kt) * 32 + lane];
                    const uint4 Ah1 = AH[((2 * wm + 1) * 8 + kt) * 32 + lane];
                    const uint4 Al0 = AL[((2 * wm + 0) * 8 + kt) * 32 + lane];
                    const uint4 Al1 = AL[((2 * wm + 1) * 8 + kt) * 32 + lane];
#pragma unroll
                    for (int j = 0; j < 2; ++j) {
                        const uint4 Bb = B2[((2 * wn + j) * 8 + kt) * 32 + lane];
                        mma16816(cf[0][j], Ah0.x, Ah0.y, Ah0.z, Ah0.w, Bb.x, Bb.y);
                        mma16816(cf[1][j], Ah1.x, Ah1.y, Ah1.z, Ah1.w, Bb.x, Bb.y);
                        mma16816(cf[0][j], Ah0.x, Ah0.y, Ah0.z, Ah0.w, Bb.z, Bb.w);
                        mma16816(cf[1][j], Ah1.x, Ah1.y, Ah1.z, Ah1.w, Bb.z, Bb.w);
                        mma16816(cf[0][j], Al0.x, Al0.y, Al0.z, Al0.w, Bb.x, Bb.y);
                        mma16816(cf[1][j], Al1.x, Al1.y, Al1.z, Al1.w, Bb.x, Bb.y);
                    }
                }
#pragma unroll
                for (int i = 0; i < 2; ++i) {
                    const int mr = m0 + 32 * wm + 16 * i + (lane >> 2);
#pragma unroll
                    for (int j = 0; j < 2; ++j) {
                        const int n0 = 8 * (2 * wn + j) + 2 * (lane & 3);
                        g_flow[(size_t)n0 * TOT + mr]           = cf[i][j][0] + bf2s[n0];
                        g_flow[(size_t)(n0 + 1) * TOT + mr]     = cf[i][j][1] + bf2s[n0 + 1];
                        g_flow[(size_t)n0 * TOT + mr + 8]       = cf[i][j][2] + bf2s[n0];
                        g_flow[(size_t)(n0 + 1) * TOT + mr + 8] = cf[i][j][3] + bf2s[n0 + 1];
                    }
                }
            }
        }
    }
}

// ---------------------------------------------------------------------------
// Kernel 3: periodic bilinear warp, 2D-tiled for gather locality.
// Value is fp16 (uint2 = 4 halves per pixel-head); interpolation in fp32.
// ---------------------------------------------------------------------------
__global__ __launch_bounds__(256) void sample_kernel(float* __restrict__ out) {
    const int lane = threadIdx.x & 31;
    const int wrp  = threadIdx.x >> 5;         // 0..7
    const int tile = blockIdx.x & 63;          // 64 tiles per plane
    const int bh   = blockIdx.x >> 6;          // b*HEADS + head
    const int head = bh & (HEADS - 1);
    const int b    = bh >> 5;
    const int col  = (tile & 7) * 32 + lane;
    const int row0 = (tile >> 3) * 32 + wrp * 4;

    const uint2* vp = (const uint2*)g_value_h + (size_t)bh * HWSZ;
    const float* fxp = g_flow + (size_t)(head * 2) * TOT + (size_t)b * HWSZ;
    const float* fyp = fxp + TOT;
    float* outp = out + ((size_t)b * COUTC + head * 4) * HWSZ;

#pragma unroll
    for (int r = 0; r < 4; ++r) {
        const int h  = row0 + r;
        const int hw = h * 256 + col;

        const float fx = fxp[hw];
        const float fy = fyp[hw];

        const float gx = -1.0f + (2.0f / 255.0f) * (float)col + fx;
        const float gy = -1.0f + (2.0f / 255.0f) * (float)h + fy;

        const float ax = ((gx + 1.0f) * 256.0f - 1.0f) * 0.5f;
        const float ay = ((gy + 1.0f) * 256.0f - 1.0f) * 0.5f;

        float px = fmodf(ax, 256.0f); if (px < 0.0f) px += 256.0f;
        float py = fmodf(ay, 256.0f); if (py < 0.0f) py += 256.0f;

        const float x0f = floorf(px), y0f = floorf(py);
        const float wx = px - x0f, wy = py - y0f;
        int x0 = (int)x0f; x0 = x0 < 0 ? 0 : (x0 > 255 ? 255 : x0);
        int y0 = (int)y0f; y0 = y0 < 0 ? 0 : (y0 > 255 ? 255 : y0);
        const int x1 = (x0 + 1) & 255;
        const int y1 = (y0 + 1) & 255;

        const uint2 q00 = vp[y0 * 256 + x0];
        const uint2 q01 = vp[y0 * 256 + x1];
        const uint2 q10 = vp[y1 * 256 + x0];
        const uint2 q11 = vp[y1 * 256 + x1];

        const float w00 = (1.0f - wx) * (1.0f - wy);
        const float w01 = wx * (1.0f - wy);
        const float w10 = (1.0f - wx) * wy;
        const float w11 = wx * wy;

        const float2 a00 = __half22float2(*(const __half2*)&q00.x);
        const float2 b00 = __half22float2(*(const __half2*)&q00.y);
        const float2 a01 = __half22float2(*(const __half2*)&q01.x);
        const float2 b01 = __half22float2(*(const __half2*)&q01.y);
        const float2 a10 = __half22float2(*(const __half2*)&q10.x);
        const float2 b10 = __half22float2(*(const __half2*)&q10.y);
        const float2 a11 = __half22float2(*(const __half2*)&q11.x);
        const float2 b11 = __half22float2(*(const __half2*)&q11.y);

        const float o0 = a00.x * w00 + a01.x * w01 + a10.x * w10 + a11.x * w11;
        const float o1 = a00.y * w00 + a01.y * w01 + a10.y * w10 + a11.y * w11;
        const float o2 = b00.x * w00 + b01.x * w01 + b10.x * w10 + b11.x * w11;
        const float o3 = b00.y * w00 + b01.y * w01 + b10.y * w10 + b11.y * w11;

        outp[hw]            = o0;
        outp[HWSZ + hw]     = o1;
        outp[2 * HWSZ + hw] = o2;
        outp[3 * HWSZ + hw] = o3;
    }
}

// ---------------------------------------------------------------------------
extern "C" void kernel_launch(void* const* d_in, const int* in_sizes, int n_in,
                              void* d_out, int out_size) {
    const float* u   = (const float*)d_in[0];
    const float* wf1 = (const float*)d_in[1];
    const float* bf1 = (const float*)d_in[2];
    const float* wf2 = (const float*)d_in[3];
    const float* bf2 = (const float*)d_in[4];
    const float* wv  = (const float*)d_in[5];
    const float* bv  = (const float*)d_in[6];
    float* out = (float*)d_out;

    cudaFuncSetAttribute(fused_gemm, cudaFuncAttributeMaxDynamicSharedMemorySize,
                         FUSED_SMEM);

    split_weights<<<16, 256>>>(wv, wf1, wf2);
    fused_gemm<<<GRID_FUSED, 512, FUSED_SMEM>>>(u, bf1, bf2, bv);

    sample_kernel<<<BQ * HEADS * 64, 256>>>(out);
}

// round 12
// speedup vs baseline: 1.0777x; 1.0777x over previous
#include <cuda_runtime.h>
#include <cuda_fp16.h>
#include <cstdint>

#define BQ    8
#define CINC  128
#define COUTC 128
#define HH    256
#define WW    256
#define HEADS 32
#define HWSZ  (HH * WW)        /* 65536 */
#define TOT   (BQ * HWSZ)      /* 524288 */
#define NPAIRS (TOT / 256)     /* 2048 */
#define GRID_FUSED 1024        /* 2 pairs per CTA, 7 CTA-waves x 2 = 14 slots */

// Scratch globals (allocation-free rule).
// g_value_h: fp16 value, [((b*32+head)*HW + hw)*2 + (ci>>1)] -> f16x2 per 2 ch
// g_flow:    [n2 * TOT + b*HW + hw]
__device__ __align__(16) uint32_t g_value_h[(size_t)TOT * HEADS * 2];
__device__ __align__(16) float g_flow[(size_t)(2 * HEADS) * TOT];

// Pre-packed fp16 weight fragments, m16n8k16 B-operand order, hi/lo fused:
// slot (nt*8 + kt)*32 + lane -> uint4 {hi_b0, hi_b1, lo_b0, lo_b1}
__device__ __align__(16) uint4 g_wv_p[4096];   // 16 ntiles
__device__ __align__(16) uint4 g_wf1_p[4096];  // 16 ntiles
__device__ __align__(16) uint4 g_wf2_p[2048];  // 8 ntiles

// ---------------------------------------------------------------------------
// helpers — fp16 hi/lo split (v ~= hi + lo, each packed f16x2, v0 -> low half)
// ---------------------------------------------------------------------------
__device__ __forceinline__ void split2(float v0, float v1, uint32_t& hi, uint32_t& lo) {
    asm("cvt.rn.f16x2.f32 %0, %1, %2;" : "=r"(hi) : "f"(v1), "f"(v0));
    float h0, h1;
    asm("{.reg .f16 x, y;\n\t mov.b32 {x, y}, %2;\n\t"
        "cvt.f32.f16 %0, x;\n\t cvt.f32.f16 %1, y;}"
        : "=f"(h0), "=f"(h1) : "r"(hi));
    const float r0 = v0 - h0;
    const float r1 = v1 - h1;
    asm("cvt.rn.f16x2.f32 %0, %1, %2;" : "=r"(lo) : "f"(r1), "f"(r0));
}
__device__ __forceinline__ uint32_t pack_h2(float v0, float v1) {
    uint32_t p;
    asm("cvt.rn.f16x2.f32 %0, %1, %2;" : "=r"(p) : "f"(v1), "f"(v0));
    return p;
}
__device__ __forceinline__ void mma16816(float* c, uint32_t a0, uint32_t a1,
                                         uint32_t a2, uint32_t a3,
                                         uint32_t b0, uint32_t b1) {
    asm volatile(
        "mma.sync.aligned.m16n8k16.row.col.f32.f16.f16.f32 "
        "{%0,%1,%2,%3}, {%4,%5,%6,%7}, {%8,%9}, {%0,%1,%2,%3};"
        : "+f"(c[0]), "+f"(c[1]), "+f"(c[2]), "+f"(c[3])
        : "r"(a0), "r"(a1), "r"(a2), "r"(a3), "r"(b0), "r"(b1));
}

// Prefetch one 128-pixel M-tile of u (512 x 128B lines) to L2. 256 thr x 2.
__device__ __forceinline__ void prefetch_tile(const float* __restrict__ uB, int t) {
#pragma unroll
    for (int j = 0; j < 2; ++j) {
        const int l = 2 * t + j;                      // 0..511
        const float* p = uB + (size_t)(l >> 2) * HWSZ + (l & 3) * 32;
        asm volatile("prefetch.global.L2 [%0];" :: "l"(p));
    }
}

// ---------------------------------------------------------------------------
// Kernel 0: pack weights into fp16 hi/lo fused B-fragments.
// ---------------------------------------------------------------------------
__global__ void split_weights(const float* __restrict__ wv,
                              const float* __restrict__ wf1,
                              const float* __restrict__ wf2) {
    const int idx  = blockIdx.x * 256 + threadIdx.x;  // 0..4095 (grid=16)
    const int lane = idx & 31;
    const int kt   = (idx >> 5) & 7;
    const int nt   = idx >> 8;          // 0..15
    const int n    = nt * 8 + (lane >> 2);
    const int k0   = kt * 16 + 2 * (lane & 3);

    {
        const float* W = wv + n * 128;
        uint4 P;
        split2(W[k0], W[k0 + 1], P.x, P.z);
        split2(W[k0 + 8], W[k0 + 9], P.y, P.w);
        g_wv_p[idx] = P;
    }
    {
        const float* W = wf1 + n * 128;
        uint4 P;
        split2(W[k0], W[k0 + 1], P.x, P.z);
        split2(W[k0 + 8], W[k0 + 9], P.y, P.w);
        g_wf1_p[idx] = P;
    }
    if (nt < 8) {
        const float* W = wf2 + n * 128;
        uint4 P;
        split2(W[k0], W[k0 + 1], P.x, P.z);
        split2(W[k0 + 8], W[k0 + 9], P.y, P.w);
        g_wf2_p[idx] = P;
    }
}

// ---------------------------------------------------------------------------
// Fused kernel v9 (R10 structure, value GEMM term-reduced): 256 threads
// (8 warps, 4m x 2n), grid 1024 / 2 pairs per CTA.
// Value GEMM uses 2 terms (Ah*Bh + Ah*Bl) — A residual term dropped; value
// is the unamplified output path and already carries fp16 storage quant of
// the same magnitude. hmid and flow GEMMs keep all 3 terms.
// MMA/warp/tile: 960 -> 832 (-13.3% on the binding HMMA pipe).
// ---------------------------------------------------------------------------
#define SM_A_HI   0
#define SM_A_LO   32768
#define SM_BV     65536
#define SM_BF1    131072
#define SM_WF2    196608
#define SM_BIASF1 229376
#define SM_BIASF2 229888
#define SM_BIASV  230144
#define FUSED_SMEM 230656

__global__ __launch_bounds__(256, 1) void fused_gemm(const float* __restrict__ u,
                                                     const float* __restrict__ bf1,
                                                     const float* __restrict__ bf2,
                                                     const float* __restrict__ bv) {
    extern __shared__ char smem[];
    const int t    = threadIdx.x;
    const int wid  = t >> 5;
    const int lane = t & 31;
    const int wm   = wid & 3;   // m group (rows 32*wm)
    const int wn   = wid >> 2;  // n group

    // prefetch first pair's tile 0 to L2; B-copy below absorbs DRAM latency.
    {
        const int base0 = blockIdx.x * 256;
        const int b0    = base0 / HWSZ;
        prefetch_tile(u + (size_t)b0 * CINC * HWSZ + (base0 - b0 * HWSZ), t);
    }

    if (t < 128) ((float*)(smem + SM_BIASF1))[t] = bf1[t];
    if (t < 64)  ((float*)(smem + SM_BIASF2))[t] = bf2[t];
    if (t < 128) ((float*)(smem + SM_BIASV))[t]  = bv[t];

    // ---- 0. copy packed weight fragments to smem ONCE per CTA ----
    {
        uint4* dv = (uint4*)(smem + SM_BV);
        uint4* df = (uint4*)(smem + SM_BF1);
        uint4* d2 = (uint4*)(smem + SM_WF2);
#pragma unroll
        for (int i = t; i < 4096; i += 256) { dv[i] = g_wv_p[i]; df[i] = g_wf1_p[i]; }
#pragma unroll
        for (int i = t; i < 2048; i += 256) { d2[i] = g_wf2_p[i]; }
    }

    const float* bf1s = (const float*)(smem + SM_BIASF1);
    const float* bf2s = (const float*)(smem + SM_BIASF2);
    const float* bvs  = (const float*)(smem + SM_BIASV);

    for (int pair = blockIdx.x; pair < NPAIRS; pair += GRID_FUSED) {
        const int base0 = pair * 256;
        const int b     = base0 / HWSZ;       // same b for both tiles
        const float* uBb = u + (size_t)b * CINC * HWSZ;

        for (int sub = 0; sub < 2; ++sub) {
            const int m0  = base0 + sub * 128;
            const int hw0 = m0 - b * HWSZ;
            const float* uB = uBb + hw0;

            __syncthreads();  // prior GEMM2 A-reads (or B copy) complete

            // ---- 1. convert A tile -> hi/lo fragments directly from gmem ----
            {
                const int kk = wid * 16 + 2 * (lane & 3);
                const float* p0 = uB + (size_t)kk * HWSZ;
                const float* p1 = uB + (size_t)(kk + 1) * HWSZ;
                const float* p2 = uB + (size_t)(kk + 8) * HWSZ;
                const float* p3 = uB + (size_t)(kk + 9) * HWSZ;
                uint4* AH = (uint4*)(smem + SM_A_HI);
                uint4* AL = (uint4*)(smem + SM_A_LO);
#pragma unroll
                for (int mt = 0; mt < 8; ++mt) {
                    const int m = mt * 16 + (lane >> 2);
                    const float f00 = p0[m],     f01 = p1[m];
                    const float f10 = p0[m + 8], f11 = p1[m + 8];
                    const float f20 = p2[m],     f21 = p3[m];
                    const float f30 = p2[m + 8], f31 = p3[m + 8];
                    uint4 H, L;
                    split2(f00, f01, H.x, L.x);
                    split2(f10, f11, H.y, L.y);
                    split2(f20, f21, H.z, L.z);
                    split2(f30, f31, H.w, L.w);
                    const int slot = (mt * 8 + wid) * 32 + lane;
                    AH[slot] = H;
                    AL[slot] = L;
                }
            }
            // prefetch next tile to L2 while this tile's GEMMs run.
            if (sub == 0) {
                prefetch_tile(uB + 128, t);
            } else {
                const int np = pair + GRID_FUSED;
                if (np < NPAIRS) {
                    const int nb0 = np * 256;
                    const int nb  = nb0 / HWSZ;
                    prefetch_tile(u + (size_t)nb * CINC * HWSZ + (nb0 - nb * HWSZ), t);
                }
            }
            __syncthreads();

            // ---- 2. value (2-term) + hmid (3-term) GEMMs fused, fp16 MMA ----
            float cv[2][8][4];
            float ch[2][8][4];
#pragma unroll
            for (int i = 0; i < 2; ++i)
#pragma unroll
                for (int nt = 0; nt < 8; ++nt)
#pragma unroll
                    for (int r = 0; r < 4; ++r) { cv[i][nt][r] = 0.0f; ch[i][nt][r] = 0.0f; }

            {
                const uint4* AH = (const uint4*)(smem + SM_A_HI);
                const uint4* AL = (const uint4*)(smem + SM_A_LO);
                const uint4* BV = (const uint4*)(smem + SM_BV);
                const uint4* BF = (const uint4*)(smem + SM_BF1);
#pragma unroll
                for (int kt = 0; kt < 8; ++kt) {
                    const uint4 Ah0 = AH[((2 * wm + 0) * 8 + kt) * 32 + lane];
                    const uint4 Ah1 = AH[((2 * wm + 1) * 8 + kt) * 32 + lane];
                    const uint4 Al0 = AL[((2 * wm + 0) * 8 + kt) * 32 + lane];
                    const uint4 Al1 = AL[((2 * wm + 1) * 8 + kt) * 32 + lane];
#pragma unroll
                    for (int nt = 0; nt < 8; ++nt) {
                        const int bslot = ((8 * wn + nt) * 8 + kt) * 32 + lane;
                        const uint4 Bv = BV[bslot];
                        const uint4 Bf = BF[bslot];
                        // value: Ah*Bh + Ah*Bl (A-residual term dropped)
                        mma16816(cv[0][nt], Ah0.x, Ah0.y, Ah0.z, Ah0.w, Bv.x, Bv.y);
                        mma16816(cv[1][nt], Ah1.x, Ah1.y, Ah1.z, Ah1.w, Bv.x, Bv.y);
                        mma16816(cv[0][nt], Ah0.x, Ah0.y, Ah0.z, Ah0.w, Bv.z, Bv.w);
                        mma16816(cv[1][nt], Ah1.x, Ah1.y, Ah1.z, Ah1.w, Bv.z, Bv.w);
                        // hmid: all 3 terms (flow path is error-amplified)
                        mma16816(ch[0][nt], Ah0.x, Ah0.y, Ah0.z, Ah0.w, Bf.x, Bf.y);
                        mma16816(ch[1][nt], Ah1.x, Ah1.y, Ah1.z, Ah1.w, Bf.x, Bf.y);
                        mma16816(ch[0][nt], Ah0.x, Ah0.y, Ah0.z, Ah0.w, Bf.z, Bf.w);
                        mma16816(ch[1][nt], Ah1.x, Ah1.y, Ah1.z, Ah1.w, Bf.z, Bf.w);
                        mma16816(ch[0][nt], Al0.x, Al0.y, Al0.z, Al0.w, Bf.x, Bf.y);
                        mma16816(ch[1][nt], Al1.x, Al1.y, Al1.z, Al1.w, Bf.x, Bf.y);
                    }
                }
            }

            // ---- 3. value epilogue -> g_value_h (f16x2 per 2 channels) ----
            {
#pragma unroll
                for (int i = 0; i < 2; ++i) {
                    const int hwr = hw0 + 32 * wm + 16 * i + (lane >> 2);
#pragma unroll
                    for (int nt = 0; nt < 8; ++nt) {
                        const int n0   = 64 * wn + 8 * nt + 2 * (lane & 3);
                        const int head = n0 >> 2;
                        const int cih  = (n0 & 3) >> 1;
                        const float bb0 = bvs[n0], bb1 = bvs[n0 + 1];
                        const size_t plane = ((size_t)b * HEADS + head) * HWSZ;
                        g_value_h[(plane + hwr) * 2 + cih] =
                            pack_h2(cv[i][nt][0] + bb0, cv[i][nt][1] + bb1);
                        g_value_h[(plane + hwr + 8) * 2 + cih] =
                            pack_h2(cv[i][nt][2] + bb0, cv[i][nt][3] + bb1);
                    }
                }
            }
            __syncthreads();  // all warps done reading A fragments

            // ---- 4. hmid -> relu -> fp16 split -> A2 fragments (reuse A) ----
            {
                uint4* AH = (uint4*)(smem + SM_A_HI);
                uint4* AL = (uint4*)(smem + SM_A_LO);
#pragma unroll
                for (int i = 0; i < 2; ++i) {
                    const int mtg = 2 * wm + i;
#pragma unroll
                    for (int kl = 0; kl < 4; ++kl) {
                        const int ktg = 4 * wn + kl;
                        const int nt0 = 2 * kl, nt1 = nt0 + 1;
                        const int n00 = 64 * wn + 8 * nt0 + 2 * (lane & 3);
                        const int n10 = n00 + 8;
                        const float b00 = bf1s[n00], b01 = bf1s[n00 + 1];
                        const float b10 = bf1s[n10], b11 = bf1s[n10 + 1];
                        uint4 H, L;
                        split2(fmaxf(ch[i][nt0][0] + b00, 0.0f),
                               fmaxf(ch[i][nt0][1] + b01, 0.0f), H.x, L.x);
                        split2(fmaxf(ch[i][nt0][2] + b00, 0.0f),
                               fmaxf(ch[i][nt0][3] + b01, 0.0f), H.y, L.y);
                        split2(fmaxf(ch[i][nt1][0] + b10, 0.0f),
                               fmaxf(ch[i][nt1][1] + b11, 0.0f), H.z, L.z);
                        split2(fmaxf(ch[i][nt1][2] + b10, 0.0f),
                               fmaxf(ch[i][nt1][3] + b11, 0.0f), H.w, L.w);
                        const int slot = (mtg * 8 + ktg) * 32 + lane;
                        AH[slot] = H;
                        AL[slot] = L;
                    }
                }
            }
            __syncthreads();

            // ---- 5. flow GEMM (N=64, warp tile 32x32, 3 terms) + epilogue ----
            {
                float cf[2][4][4];
#pragma unroll
                for (int i = 0; i < 2; ++i)
#pragma unroll
                    for (int j = 0; j < 4; ++j)
#pragma unroll
                        for (int r = 0; r < 4; ++r) cf[i][j][r] = 0.0f;

                const uint4* AH = (const uint4*)(smem + SM_A_HI);
                const uint4* AL = (const uint4*)(smem + SM_A_LO);
                const uint4* B2 = (const uint4*)(smem + SM_WF2);
#pragma unroll
                for (int kt = 0; kt < 8; ++kt) {
                    const uint4 Ah0 = AH[((2 * wm + 0) * 8 + kt) * 32 + lane];
                    const uint4 Ah1 = AH[((2 * wm + 1) * 8 + kt) * 32 + lane];
                    const uint4 Al0 = AL[((2 * wm + 0) * 8 + kt) * 32 + lane];
                    const uint4 Al1 = AL[((2 * wm + 1) * 8 + kt) * 32 + lane];
#pragma unroll
                    for (int j = 0; j < 4; ++j) {
                        const uint4 Bb = B2[((4 * wn + j) * 8 + kt) * 32 + lane];
                        mma16816(cf[0][j], Ah0.x, Ah0.y, Ah0.z, Ah0.w, Bb.x, Bb.y);
                        mma16816(cf[1][j], Ah1.x, Ah1.y, Ah1.z, Ah1.w, Bb.x, Bb.y);
                        mma16816(cf[0][j], Ah0.x, Ah0.y, Ah0.z, Ah0.w, Bb.z, Bb.w);
                        mma16816(cf[1][j], Ah1.x, Ah1.y, Ah1.z, Ah1.w, Bb.z, Bb.w);
                        mma16816(cf[0][j], Al0.x, Al0.y, Al0.z, Al0.w, Bb.x, Bb.y);
                        mma16816(cf[1][j], Al1.x, Al1.y, Al1.z, Al1.w, Bb.x, Bb.y);
                    }
                }
#pragma unroll
                for (int i = 0; i < 2; ++i) {
                    const int mr = m0 + 32 * wm + 16 * i + (lane >> 2);
#pragma unroll
                    for (int j = 0; j < 4; ++j) {
                        const int n0 = 32 * wn + 8 * j + 2 * (lane & 3);
                        g_flow[(size_t)n0 * TOT + mr]           = cf[i][j][0] + bf2s[n0];
                        g_flow[(size_t)(n0 + 1) * TOT + mr]     = cf[i][j][1] + bf2s[n0 + 1];
                        g_flow[(size_t)n0 * TOT + mr + 8]       = cf[i][j][2] + bf2s[n0];
                        g_flow[(size_t)(n0 + 1) * TOT + mr + 8] = cf[i][j][3] + bf2s[n0 + 1];
                    }
                }
            }
        }
    }
}

// ---------------------------------------------------------------------------
// Kernel 3: periodic bilinear warp, 2D-tiled for gather locality.
// Value is fp16 (uint2 = 4 halves per pixel-head); interpolation in fp32.
// ---------------------------------------------------------------------------
__global__ __launch_bounds__(256) void sample_kernel(float* __restrict__ out) {
    const int lane = threadIdx.x & 31;
    const int wrp  = threadIdx.x >> 5;         // 0..7
    const int tile = blockIdx.x & 63;          // 64 tiles per plane
    const int bh   = blockIdx.x >> 6;          // b*HEADS + head
    const int head = bh & (HEADS - 1);
    const int b    = bh >> 5;
    const int col  = (tile & 7) * 32 + lane;
    const int row0 = (tile >> 3) * 32 + wrp * 4;

    const uint2* vp = (const uint2*)g_value_h + (size_t)bh * HWSZ;
    const float* fxp = g_flow + (size_t)(head * 2) * TOT + (size_t)b * HWSZ;
    const float* fyp = fxp + TOT;
    float* outp = out + ((size_t)b * COUTC + head * 4) * HWSZ;

#pragma unroll
    for (int r = 0; r < 4; ++r) {
        const int h  = row0 + r;
        const int hw = h * 256 + col;

        const float fx = fxp[hw];
        const float fy = fyp[hw];

        const float gx = -1.0f + (2.0f / 255.0f) * (float)col + fx;
        const float gy = -1.0f + (2.0f / 255.0f) * (float)h + fy;

        const float ax = ((gx + 1.0f) * 256.0f - 1.0f) * 0.5f;
        const float ay = ((gy + 1.0f) * 256.0f - 1.0f) * 0.5f;

        float px = fmodf(ax, 256.0f); if (px < 0.0f) px += 256.0f;
        float py = fmodf(ay, 256.0f); if (py < 0.0f) py += 256.0f;

        const float x0f = floorf(px), y0f = floorf(py);
        const float wx = px - x0f, wy = py - y0f;
        int x0 = (int)x0f; x0 = x0 < 0 ? 0 : (x0 > 255 ? 255 : x0);
        int y0 = (int)y0f; y0 = y0 < 0 ? 0 : (y0 > 255 ? 255 : y0);
        const int x1 = (x0 + 1) & 255;
        const int y1 = (y0 + 1) & 255;

        const uint2 q00 = vp[y0 * 256 + x0];
        const uint2 q01 = vp[y0 * 256 + x1];
        const uint2 q10 = vp[y1 * 256 + x0];
        const uint2 q11 = vp[y1 * 256 + x1];

        const float w00 = (1.0f - wx) * (1.0f - wy);
        const float w01 = wx * (1.0f - wy);
        const float w10 = (1.0f - wx) * wy;
        const float w11 = wx * wy;

        const float2 a00 = __half22float2(*(const __half2*)&q00.x);
        const float2 b00 = __half22float2(*(const __half2*)&q00.y);
        const float2 a01 = __half22float2(*(const __half2*)&q01.x);
        const float2 b01 = __half22float2(*(const __half2*)&q01.y);
        const float2 a10 = __half22float2(*(const __half2*)&q10.x);
        const float2 b10 = __half22float2(*(const __half2*)&q10.y);
        const float2 a11 = __half22float2(*(const __half2*)&q11.x);
        const float2 b11 = __half22float2(*(const __half2*)&q11.y);

        const float o0 = a00.x * w00 + a01.x * w01 + a10.x * w10 + a11.x * w11;
        const float o1 = a00.y * w00 + a01.y * w01 + a10.y * w10 + a11.y * w11;
        const float o2 = b00.x * w00 + b01.x * w01 + b10.x * w10 + b11.x * w11;
        const float o3 = b00.y * w00 + b01.y * w01 + b10.y * w10 + b11.y * w11;

        outp[hw]            = o0;
        outp[HWSZ + hw]     = o1;
        outp[2 * HWSZ + hw] = o2;
        outp[3 * HWSZ + hw] = o3;
    }
}

// ---------------------------------------------------------------------------
extern "C" void kernel_launch(void* const* d_in, const int* in_sizes, int n_in,
                              void* d_out, int out_size) {
    const float* u   = (const float*)d_in[0];
    const float* wf1 = (const float*)d_in[1];
    const float* bf1 = (const float*)d_in[2];
    const float* wf2 = (const float*)d_in[3];
    const float* bf2 = (const float*)d_in[4];
    const float* wv  = (const float*)d_in[5];
    const float* bv  = (const float*)d_in[6];
    float* out = (float*)d_out;

    cudaFuncSetAttribute(fused_gemm, cudaFuncAttributeMaxDynamicSharedMemorySize,
                         FUSED_SMEM);

    split_weights<<<16, 256>>>(wv, wf1, wf2);
    fused_gemm<<<GRID_FUSED, 256, FUSED_SMEM>>>(u, bf1, bf2, bv);

    sample_kernel<<<BQ * HEADS * 64, 256>>>(out);
}

// round 13
// speedup vs baseline: 1.1517x; 1.0687x over previous
#include <cuda_runtime.h>
#include <cuda_fp16.h>
#include <cstdint>

#define BQ    8
#define CINC  128
#define COUTC 128
#define HH    256
#define WW    256
#define HEADS 32
#define HWSZ  (HH * WW)        /* 65536 */
#define TOT   (BQ * HWSZ)      /* 524288 */
#define NPAIRS (TOT / 256)     /* 2048 */
#define GRID_FUSED 1024        /* 2 pairs per CTA, 7 CTA-waves x 2 = 14 slots */

// Scratch globals (allocation-free rule).
// g_value_h: fp16 value, [((b*32+head)*HW + hw)*2 + (ci>>1)] -> f16x2 per 2 ch
// g_flow:    [n2 * TOT + b*HW + hw]
__device__ __align__(16) uint32_t g_value_h[(size_t)TOT * HEADS * 2];
__device__ __align__(16) float g_flow[(size_t)(2 * HEADS) * TOT];

// Pre-packed fp16 weight fragments, m16n8k16 B-operand order, hi/lo fused:
// slot (nt*8 + kt)*32 + lane -> uint4 {hi_b0, hi_b1, lo_b0, lo_b1}
__device__ __align__(16) uint4 g_wv_p[4096];   // 16 ntiles (only hi half used now)
__device__ __align__(16) uint4 g_wf1_p[4096];  // 16 ntiles
__device__ __align__(16) uint4 g_wf2_p[2048];  // 8 ntiles

// ---------------------------------------------------------------------------
// helpers — fp16 hi/lo split (v ~= hi + lo, each packed f16x2, v0 -> low half)
// ---------------------------------------------------------------------------
__device__ __forceinline__ void split2(float v0, float v1, uint32_t& hi, uint32_t& lo) {
    asm("cvt.rn.f16x2.f32 %0, %1, %2;" : "=r"(hi) : "f"(v1), "f"(v0));
    float h0, h1;
    asm("{.reg .f16 x, y;\n\t mov.b32 {x, y}, %2;\n\t"
        "cvt.f32.f16 %0, x;\n\t cvt.f32.f16 %1, y;}"
        : "=f"(h0), "=f"(h1) : "r"(hi));
    const float r0 = v0 - h0;
    const float r1 = v1 - h1;
    asm("cvt.rn.f16x2.f32 %0, %1, %2;" : "=r"(lo) : "f"(r1), "f"(r0));
}
__device__ __forceinline__ uint32_t pack_h2(float v0, float v1) {
    uint32_t p;
    asm("cvt.rn.f16x2.f32 %0, %1, %2;" : "=r"(p) : "f"(v1), "f"(v0));
    return p;
}
__device__ __forceinline__ void mma16816(float* c, uint32_t a0, uint32_t a1,
                                         uint32_t a2, uint32_t a3,
                                         uint32_t b0, uint32_t b1) {
    asm volatile(
        "mma.sync.aligned.m16n8k16.row.col.f32.f16.f16.f32 "
        "{%0,%1,%2,%3}, {%4,%5,%6,%7}, {%8,%9}, {%0,%1,%2,%3};"
        : "+f"(c[0]), "+f"(c[1]), "+f"(c[2]), "+f"(c[3])
        : "r"(a0), "r"(a1), "r"(a2), "r"(a3), "r"(b0), "r"(b1));
}

// Prefetch one 128-pixel M-tile of u (512 x 128B lines) to L2. 256 thr x 2.
__device__ __forceinline__ void prefetch_tile(const float* __restrict__ uB, int t) {
#pragma unroll
    for (int j = 0; j < 2; ++j) {
        const int l = 2 * t + j;                      // 0..511
        const float* p = uB + (size_t)(l >> 2) * HWSZ + (l & 3) * 32;
        asm volatile("prefetch.global.L2 [%0];" :: "l"(p));
    }
}

// ---------------------------------------------------------------------------
// Kernel 0: pack weights into fp16 hi/lo fused B-fragments.
// ---------------------------------------------------------------------------
__global__ void split_weights(const float* __restrict__ wv,
                              const float* __restrict__ wf1,
                              const float* __restrict__ wf2) {
    const int idx  = blockIdx.x * 256 + threadIdx.x;  // 0..4095 (grid=16)
    const int lane = idx & 31;
    const int kt   = (idx >> 5) & 7;
    const int nt   = idx >> 8;          // 0..15
    const int n    = nt * 8 + (lane >> 2);
    const int k0   = kt * 16 + 2 * (lane & 3);

    {
        const float* W = wv + n * 128;
        uint4 P;
        split2(W[k0], W[k0 + 1], P.x, P.z);
        split2(W[k0 + 8], W[k0 + 9], P.y, P.w);
        g_wv_p[idx] = P;
    }
    {
        const float* W = wf1 + n * 128;
        uint4 P;
        split2(W[k0], W[k0 + 1], P.x, P.z);
        split2(W[k0 + 8], W[k0 + 9], P.y, P.w);
        g_wf1_p[idx] = P;
    }
    if (nt < 8) {
        const float* W = wf2 + n * 128;
        uint4 P;
        split2(W[k0], W[k0 + 1], P.x, P.z);
        split2(W[k0 + 8], W[k0 + 9], P.y, P.w);
        g_wf2_p[idx] = P;
    }
}

// ---------------------------------------------------------------------------
// Fused kernel v10: value GEMM now 1 term (Ah*Bh) — plain fp16 GEMM; value is
// the unamplified output path and already carries fp16 storage quantization
// of the same magnitude class. hmid + flow GEMMs keep all 3 fp16x3 terms
// (flow path is error-amplified ~5-50x through pixel coordinates).
// MMA/warp/tile: 832 -> 704 (-15.4% on the binding HMMA pipe).
// 256 threads (8 warps, 4m x 2n), grid 1024 / 2 pairs per CTA, 1 CTA/SM.
// ---------------------------------------------------------------------------
#define SM_A_HI   0
#define SM_A_LO   32768
#define SM_BV     65536
#define SM_BF1    131072
#define SM_WF2    196608
#define SM_BIASF1 229376
#define SM_BIASF2 229888
#define SM_BIASV  230144
#define FUSED_SMEM 230656

__global__ __launch_bounds__(256, 1) void fused_gemm(const float* __restrict__ u,
                                                     const float* __restrict__ bf1,
                                                     const float* __restrict__ bf2,
                                                     const float* __restrict__ bv) {
    extern __shared__ char smem[];
    const int t    = threadIdx.x;
    const int wid  = t >> 5;
    const int lane = t & 31;
    const int wm   = wid & 3;   // m group (rows 32*wm)
    const int wn   = wid >> 2;  // n group

    // prefetch first pair's tile 0 to L2; B-copy below absorbs DRAM latency.
    {
        const int base0 = blockIdx.x * 256;
        const int b0    = base0 / HWSZ;
        prefetch_tile(u + (size_t)b0 * CINC * HWSZ + (base0 - b0 * HWSZ), t);
    }

    if (t < 128) ((float*)(smem + SM_BIASF1))[t] = bf1[t];
    if (t < 64)  ((float*)(smem + SM_BIASF2))[t] = bf2[t];
    if (t < 128) ((float*)(smem + SM_BIASV))[t]  = bv[t];

    // ---- 0. copy packed weight fragments to smem ONCE per CTA ----
    {
        uint4* dv = (uint4*)(smem + SM_BV);
        uint4* df = (uint4*)(smem + SM_BF1);
        uint4* d2 = (uint4*)(smem + SM_WF2);
#pragma unroll
        for (int i = t; i < 4096; i += 256) { dv[i] = g_wv_p[i]; df[i] = g_wf1_p[i]; }
#pragma unroll
        for (int i = t; i < 2048; i += 256) { d2[i] = g_wf2_p[i]; }
    }

    const float* bf1s = (const float*)(smem + SM_BIASF1);
    const float* bf2s = (const float*)(smem + SM_BIASF2);
    const float* bvs  = (const float*)(smem + SM_BIASV);

    for (int pair = blockIdx.x; pair < NPAIRS; pair += GRID_FUSED) {
        const int base0 = pair * 256;
        const int b     = base0 / HWSZ;       // same b for both tiles
        const float* uBb = u + (size_t)b * CINC * HWSZ;

        for (int sub = 0; sub < 2; ++sub) {
            const int m0  = base0 + sub * 128;
            const int hw0 = m0 - b * HWSZ;
            const float* uB = uBb + hw0;

            __syncthreads();  // prior GEMM2 A-reads (or B copy) complete

            // ---- 1. convert A tile -> hi/lo fragments directly from gmem ----
            {
                const int kk = wid * 16 + 2 * (lane & 3);
                const float* p0 = uB + (size_t)kk * HWSZ;
                const float* p1 = uB + (size_t)(kk + 1) * HWSZ;
                const float* p2 = uB + (size_t)(kk + 8) * HWSZ;
                const float* p3 = uB + (size_t)(kk + 9) * HWSZ;
                uint4* AH = (uint4*)(smem + SM_A_HI);
                uint4* AL = (uint4*)(smem + SM_A_LO);
#pragma unroll
                for (int mt = 0; mt < 8; ++mt) {
                    const int m = mt * 16 + (lane >> 2);
                    const float f00 = p0[m],     f01 = p1[m];
                    const float f10 = p0[m + 8], f11 = p1[m + 8];
                    const float f20 = p2[m],     f21 = p3[m];
                    const float f30 = p2[m + 8], f31 = p3[m + 8];
                    uint4 H, L;
                    split2(f00, f01, H.x, L.x);
                    split2(f10, f11, H.y, L.y);
                    split2(f20, f21, H.z, L.z);
                    split2(f30, f31, H.w, L.w);
                    const int slot = (mt * 8 + wid) * 32 + lane;
                    AH[slot] = H;
                    AL[slot] = L;
                }
            }
            // prefetch next tile to L2 while this tile's GEMMs run.
            if (sub == 0) {
                prefetch_tile(uB + 128, t);
            } else {
                const int np = pair + GRID_FUSED;
                if (np < NPAIRS) {
                    const int nb0 = np * 256;
                    const int nb  = nb0 / HWSZ;
                    prefetch_tile(u + (size_t)nb * CINC * HWSZ + (nb0 - nb * HWSZ), t);
                }
            }
            __syncthreads();

            // ---- 2. value (1-term) + hmid (3-term) GEMMs fused, fp16 MMA ----
            float cv[2][8][4];
            float ch[2][8][4];
#pragma unroll
            for (int i = 0; i < 2; ++i)
#pragma unroll
                for (int nt = 0; nt < 8; ++nt)
#pragma unroll
                    for (int r = 0; r < 4; ++r) { cv[i][nt][r] = 0.0f; ch[i][nt][r] = 0.0f; }

            {
                const uint4* AH = (const uint4*)(smem + SM_A_HI);
                const uint4* AL = (const uint4*)(smem + SM_A_LO);
                const uint2* BV = (const uint2*)(smem + SM_BV);   // hi half only
                const uint4* BF = (const uint4*)(smem + SM_BF1);
#pragma unroll
                for (int kt = 0; kt < 8; ++kt) {
                    const uint4 Ah0 = AH[((2 * wm + 0) * 8 + kt) * 32 + lane];
                    const uint4 Ah1 = AH[((2 * wm + 1) * 8 + kt) * 32 + lane];
                    const uint4 Al0 = AL[((2 * wm + 0) * 8 + kt) * 32 + lane];
                    const uint4 Al1 = AL[((2 * wm + 1) * 8 + kt) * 32 + lane];
#pragma unroll
                    for (int nt = 0; nt < 8; ++nt) {
                        const int bslot = ((8 * wn + nt) * 8 + kt) * 32 + lane;
                        const uint2 Bv = BV[2 * bslot];   // first 8B of uint4 slot
                        const uint4 Bf = BF[bslot];
                        // value: Ah*Bh only (plain fp16 GEMM, unamplified path)
                        mma16816(cv[0][nt], Ah0.x, Ah0.y, Ah0.z, Ah0.w, Bv.x, Bv.y);
                        mma16816(cv[1][nt], Ah1.x, Ah1.y, Ah1.z, Ah1.w, Bv.x, Bv.y);
                        // hmid: all 3 terms (flow path is error-amplified)
                        mma16816(ch[0][nt], Ah0.x, Ah0.y, Ah0.z, Ah0.w, Bf.x, Bf.y);
                        mma16816(ch[1][nt], Ah1.x, Ah1.y, Ah1.z, Ah1.w, Bf.x, Bf.y);
                        mma16816(ch[0][nt], Ah0.x, Ah0.y, Ah0.z, Ah0.w, Bf.z, Bf.w);
                        mma16816(ch[1][nt], Ah1.x, Ah1.y, Ah1.z, Ah1.w, Bf.z, Bf.w);
                        mma16816(ch[0][nt], Al0.x, Al0.y, Al0.z, Al0.w, Bf.x, Bf.y);
                        mma16816(ch[1][nt], Al1.x, Al1.y, Al1.z, Al1.w, Bf.x, Bf.y);
                    }
                }
            }

            // ---- 3. value epilogue -> g_value_h (f16x2 per 2 channels) ----
            {
#pragma unroll
                for (int i = 0; i < 2; ++i) {
                    const int hwr = hw0 + 32 * wm + 16 * i + (lane >> 2);
#pragma unroll
                    for (int nt = 0; nt < 8; ++nt) {
                        const int n0   = 64 * wn + 8 * nt + 2 * (lane & 3);
                        const int head = n0 >> 2;
                        const int cih  = (n0 & 3) >> 1;
                        const float bb0 = bvs[n0], bb1 = bvs[n0 + 1];
                        const size_t plane = ((size_t)b * HEADS + head) * HWSZ;
                        g_value_h[(plane + hwr) * 2 + cih] =
                            pack_h2(cv[i][nt][0] + bb0, cv[i][nt][1] + bb1);
                        g_value_h[(plane + hwr + 8) * 2 + cih] =
                            pack_h2(cv[i][nt][2] + bb0, cv[i][nt][3] + bb1);
                    }
                }
            }
            __syncthreads();  // all warps done reading A fragments

            // ---- 4. hmid -> relu -> fp16 split -> A2 fragments (reuse A) ----
            {
                uint4* AH = (uint4*)(smem + SM_A_HI);
                uint4* AL = (uint4*)(smem + SM_A_LO);
#pragma unroll
                for (int i = 0; i < 2; ++i) {
                    const int mtg = 2 * wm + i;
#pragma unroll
                    for (int kl = 0; kl < 4; ++kl) {
                        const int ktg = 4 * wn + kl;
                        const int nt0 = 2 * kl, nt1 = nt0 + 1;
                        const int n00 = 64 * wn + 8 * nt0 + 2 * (lane & 3);
                        const int n10 = n00 + 8;
                        const float b00 = bf1s[n00], b01 = bf1s[n00 + 1];
                        const float b10 = bf1s[n10], b11 = bf1s[n10 + 1];
                        uint4 H, L;
                        split2(fmaxf(ch[i][nt0][0] + b00, 0.0f),
                               fmaxf(ch[i][nt0][1] + b01, 0.0f), H.x, L.x);
                        split2(fmaxf(ch[i][nt0][2] + b00, 0.0f),
                               fmaxf(ch[i][nt0][3] + b01, 0.0f), H.y, L.y);
                        split2(fmaxf(ch[i][nt1][0] + b10, 0.0f),
                               fmaxf(ch[i][nt1][1] + b11, 0.0f), H.z, L.z);
                        split2(fmaxf(ch[i][nt1][2] + b10, 0.0f),
                               fmaxf(ch[i][nt1][3] + b11, 0.0f), H.w, L.w);
                        const int slot = (mtg * 8 + ktg) * 32 + lane;
                        AH[slot] = H;
                        AL[slot] = L;
                    }
                }
            }
            __syncthreads();

            // ---- 5. flow GEMM (N=64, warp tile 32x32, 3 terms) + epilogue ----
            {
                float cf[2][4][4];
#pragma unroll
                for (int i = 0; i < 2; ++i)
#pragma unroll
                    for (int j = 0; j < 4; ++j)
#pragma unroll
                        for (int r = 0; r < 4; ++r) cf[i][j][r] = 0.0f;

                const uint4* AH = (const uint4*)(smem + SM_A_HI);
                const uint4* AL = (const uint4*)(smem + SM_A_LO);
                const uint4* B2 = (const uint4*)(smem + SM_WF2);
#pragma unroll
                for (int kt = 0; kt < 8; ++kt) {
                    const uint4 Ah0 = AH[((2 * wm + 0) * 8 + kt) * 32 + lane];
                    const uint4 Ah1 = AH[((2 * wm + 1) * 8 + kt) * 32 + lane];
                    const uint4 Al0 = AL[((2 * wm + 0) * 8 + kt) * 32 + lane];
                    const uint4 Al1 = AL[((2 * wm + 1) * 8 + kt) * 32 + lane];
#pragma unroll
                    for (int j = 0; j < 4; ++j) {
                        const uint4 Bb = B2[((4 * wn + j) * 8 + kt) * 32 + lane];
                        mma16816(cf[0][j], Ah0.x, Ah0.y, Ah0.z, Ah0.w, Bb.x, Bb.y);
                        mma16816(cf[1][j], Ah1.x, Ah1.y, Ah1.z, Ah1.w, Bb.x, Bb.y);
                        mma16816(cf[0][j], Ah0.x, Ah0.y, Ah0.z, Ah0.w, Bb.z, Bb.w);
                        mma16816(cf[1][j], Ah1.x, Ah1.y, Ah1.z, Ah1.w, Bb.z, Bb.w);
                        mma16816(cf[0][j], Al0.x, Al0.y, Al0.z, Al0.w, Bb.x, Bb.y);
                        mma16816(cf[1][j], Al1.x, Al1.y, Al1.z, Al1.w, Bb.x, Bb.y);
                    }
                }
#pragma unroll
                for (int i = 0; i < 2; ++i) {
                    const int mr = m0 + 32 * wm + 16 * i + (lane >> 2);
#pragma unroll
                    for (int j = 0; j < 4; ++j) {
                        const int n0 = 32 * wn + 8 * j + 2 * (lane & 3);
                        g_flow[(size_t)n0 * TOT + mr]           = cf[i][j][0] + bf2s[n0];
                        g_flow[(size_t)(n0 + 1) * TOT + mr]     = cf[i][j][1] + bf2s[n0 + 1];
                        g_flow[(size_t)n0 * TOT + mr + 8]       = cf[i][j][2] + bf2s[n0];
                        g_flow[(size_t)(n0 + 1) * TOT + mr + 8] = cf[i][j][3] + bf2s[n0 + 1];
                    }
                }
            }
        }
    }
}

// ---------------------------------------------------------------------------
// Kernel 3: periodic bilinear warp, 2D-tiled for gather locality.
// Value is fp16 (uint2 = 4 halves per pixel-head); interpolation in fp32.
// ---------------------------------------------------------------------------
__global__ __launch_bounds__(256) void sample_kernel(float* __restrict__ out) {
    const int lane = threadIdx.x & 31;
    const int wrp  = threadIdx.x >> 5;         // 0..7
    const int tile = blockIdx.x & 63;          // 64 tiles per plane
    const int bh   = blockIdx.x >> 6;          // b*HEADS + head
    const int head = bh & (HEADS - 1);
    const int b    = bh >> 5;
    const int col  = (tile & 7) * 32 + lane;
    const int row0 = (tile >> 3) * 32 + wrp * 4;

    const uint2* vp = (const uint2*)g_value_h + (size_t)bh * HWSZ;
    const float* fxp = g_flow + (size_t)(head * 2) * TOT + (size_t)b * HWSZ;
    const float* fyp = fxp + TOT;
    float* outp = out + ((size_t)b * COUTC + head * 4) * HWSZ;

#pragma unroll
    for (int r = 0; r < 4; ++r) {
        const int h  = row0 + r;
        const int hw = h * 256 + col;

        const float fx = fxp[hw];
        const float fy = fyp[hw];

        const float gx = -1.0f + (2.0f / 255.0f) * (float)col + fx;
        const float gy = -1.0f + (2.0f / 255.0f) * (float)h + fy;

        const float ax = ((gx + 1.0f) * 256.0f - 1.0f) * 0.5f;
        const float ay = ((gy + 1.0f) * 256.0f - 1.0f) * 0.5f;

        float px = fmodf(ax, 256.0f); if (px < 0.0f) px += 256.0f;
        float py = fmodf(ay, 256.0f); if (py < 0.0f) py += 256.0f;

        const float x0f = floorf(px), y0f = floorf(py);
        const float wx = px - x0f, wy = py - y0f;
        int x0 = (int)x0f; x0 = x0 < 0 ? 0 : (x0 > 255 ? 255 : x0);
        int y0 = (int)y0f; y0 = y0 < 0 ? 0 : (y0 > 255 ? 255 : y0);
        const int x1 = (x0 + 1) & 255;
        const int y1 = (y0 + 1) & 255;

        const uint2 q00 = vp[y0 * 256 + x0];
        const uint2 q01 = vp[y0 * 256 + x1];
        const uint2 q10 = vp[y1 * 256 + x0];
        const uint2 q11 = vp[y1 * 256 + x1];

        const float w00 = (1.0f - wx) * (1.0f - wy);
        const float w01 = wx * (1.0f - wy);
        const float w10 = (1.0f - wx) * wy;
        const float w11 = wx * wy;

        const float2 a00 = __half22float2(*(const __half2*)&q00.x);
        const float2 b00 = __half22float2(*(const __half2*)&q00.y);
        const float2 a01 = __half22float2(*(const __half2*)&q01.x);
        const float2 b01 = __half22float2(*(const __half2*)&q01.y);
        const float2 a10 = __half22float2(*(const __half2*)&q10.x);
        const float2 b10 = __half22float2(*(const __half2*)&q10.y);
        const float2 a11 = __half22float2(*(const __half2*)&q11.x);
        const float2 b11 = __half22float2(*(const __half2*)&q11.y);

        const float o0 = a00.x * w00 + a01.x * w01 + a10.x * w10 + a11.x * w11;
        const float o1 = a00.y * w00 + a01.y * w01 + a10.y * w10 + a11.y * w11;
        const float o2 = b00.x * w00 + b01.x * w01 + b10.x * w10 + b11.x * w11;
        const float o3 = b00.y * w00 + b01.y * w01 + b10.y * w10 + b11.y * w11;

        outp[hw]            = o0;
        outp[HWSZ + hw]     = o1;
        outp[2 * HWSZ + hw] = o2;
        outp[3 * HWSZ + hw] = o3;
    }
}

// ---------------------------------------------------------------------------
extern "C" void kernel_launch(void* const* d_in, const int* in_sizes, int n_in,
                              void* d_out, int out_size) {
    const float* u   = (const float*)d_in[0];
    const float* wf1 = (const float*)d_in[1];
    const float* bf1 = (const float*)d_in[2];
    const float* wf2 = (const float*)d_in[3];
    const float* bf2 = (const float*)d_in[4];
    const float* wv  = (const float*)d_in[5];
    const float* bv  = (const float*)d_in[6];
    float* out = (float*)d_out;

    cudaFuncSetAttribute(fused_gemm, cudaFuncAttributeMaxDynamicSharedMemorySize,
                         FUSED_SMEM);

    split_weights<<<16, 256>>>(wv, wf1, wf2);
    fused_gemm<<<GRID_FUSED, 256, FUSED_SMEM>>>(u, bf1, bf2, bv);

    sample_kernel<<<BQ * HEADS * 64, 256>>>(out);
}

// round 14
// speedup vs baseline: 1.1659x; 1.0124x over previous
#include <cuda_runtime.h>
#include <cuda_fp16.h>
#include <cstdint>

#define BQ    8
#define CINC  128
#define COUTC 128
#define HH    256
#define WW    256
#define HEADS 32
#define HWSZ  (HH * WW)        /* 65536 */
#define TOT   (BQ * HWSZ)      /* 524288 */
#define NPAIRS (TOT / 256)     /* 2048 */
#define GRID_FUSED 1024        /* 2 pairs per CTA, 7 CTA-waves x 2 = 14 slots */

// Scratch globals (allocation-free rule).
__device__ __align__(16) uint32_t g_value_h[(size_t)TOT * HEADS * 2];
__device__ __align__(16) float g_flow[(size_t)(2 * HEADS) * TOT];

// Pre-packed fp16 weight fragments, m16n8k16 B-operand order.
// wv: hi-only uint2 {hi_b0, hi_b1}; wf1/wf2: uint4 {hi_b0, hi_b1, lo_b0, lo_b1}
__device__ __align__(16) uint2 g_wv_p[4096];   // 16 ntiles, hi only (32KB)
__device__ __align__(16) uint4 g_wf1_p[4096];  // 16 ntiles
__device__ __align__(16) uint4 g_wf2_p[2048];  // 8 ntiles

// ---------------------------------------------------------------------------
// helpers — fp16 hi/lo split (v ~= hi + lo, each packed f16x2, v0 -> low half)
// ---------------------------------------------------------------------------
__device__ __forceinline__ void split2(float v0, float v1, uint32_t& hi, uint32_t& lo) {
    asm("cvt.rn.f16x2.f32 %0, %1, %2;" : "=r"(hi) : "f"(v1), "f"(v0));
    float h0, h1;
    asm("{.reg .f16 x, y;\n\t mov.b32 {x, y}, %2;\n\t"
        "cvt.f32.f16 %0, x;\n\t cvt.f32.f16 %1, y;}"
        : "=f"(h0), "=f"(h1) : "r"(hi));
    const float r0 = v0 - h0;
    const float r1 = v1 - h1;
    asm("cvt.rn.f16x2.f32 %0, %1, %2;" : "=r"(lo) : "f"(r1), "f"(r0));
}
__device__ __forceinline__ uint32_t pack_h2(float v0, float v1) {
    uint32_t p;
    asm("cvt.rn.f16x2.f32 %0, %1, %2;" : "=r"(p) : "f"(v1), "f"(v0));
    return p;
}
__device__ __forceinline__ void mma16816(float* c, uint32_t a0, uint32_t a1,
                                         uint32_t a2, uint32_t a3,
                                         uint32_t b0, uint32_t b1) {
    asm volatile(
        "mma.sync.aligned.m16n8k16.row.col.f32.f16.f16.f32 "
        "{%0,%1,%2,%3}, {%4,%5,%6,%7}, {%8,%9}, {%0,%1,%2,%3};"
        : "+f"(c[0]), "+f"(c[1]), "+f"(c[2]), "+f"(c[3])
        : "r"(a0), "r"(a1), "r"(a2), "r"(a3), "r"(b0), "r"(b1));
}

// ---------------------------------------------------------------------------
// SMEM map (bytes):
//  A_HI 0 (32K) | A_LO 32768 (32K) | BV 65536 (32K, uint2) |
//  BF1 98304 (64K) | WF2 163840 (32K) | STAGE 196608 (64k x 132 f32 = 33792) |
//  biases @230400. Total 231680 <= 232448.
// ---------------------------------------------------------------------------
#define SM_A_HI   0
#define SM_A_LO   32768
#define SM_BV     65536
#define SM_BF1    98304
#define SM_WF2    163840
#define SM_STAGE  196608
#define SM_BIASF1 230400
#define SM_BIASF2 230912
#define SM_BIASV  231168
#define FUSED_SMEM 231680

// Stage k in [0,64) of one 128-pixel M-tile of u into SMEM via cp.async.
// 2048 x 16B copies; 256 threads x 8. Pitch 132 floats (conflict-free reads).
__device__ __forceinline__ void stage_issue(const float* __restrict__ uB,
                                            char* smem, int t) {
#pragma unroll
    for (int r = 0; r < 8; ++r) {
        const int idx = t + r * 256;       // 0..2047
        const int k   = idx >> 5;          // 0..63
        const int mc  = idx & 31;          // 16B chunk within 512B row
        const uint32_t dst = (uint32_t)__cvta_generic_to_shared(
            smem + SM_STAGE + (k * 132 + mc * 4) * 4);
        asm volatile("cp.async.ca.shared.global [%0], [%1], 16;"
                     :: "r"(dst), "l"(uB + (size_t)k * HWSZ + mc * 4));
    }
    asm volatile("cp.async.commit_group;" ::: "memory");
}
// Prefetch k in [64,128) of a tile to L2 (256 x 128B lines, 1 per thread).
__device__ __forceinline__ void prefetch_hi(const float* __restrict__ uB, int t) {
    const int k = 64 + (t >> 2);
    const float* p = uB + (size_t)k * HWSZ + (t & 3) * 32;
    asm volatile("prefetch.global.L2 [%0];" :: "l"(p));
}

// ---------------------------------------------------------------------------
// Kernel 0: pack weights into fp16 B-fragments (wv hi-only).
// ---------------------------------------------------------------------------
__global__ void split_weights(const float* __restrict__ wv,
                              const float* __restrict__ wf1,
                              const float* __restrict__ wf2) {
    const int idx  = blockIdx.x * 256 + threadIdx.x;  // 0..4095 (grid=16)
    const int lane = idx & 31;
    const int kt   = (idx >> 5) & 7;
    const int nt   = idx >> 8;          // 0..15
    const int n    = nt * 8 + (lane >> 2);
    const int k0   = kt * 16 + 2 * (lane & 3);

    {
        const float* W = wv + n * 128;
        uint32_t h0, l0, h1, l1;
        split2(W[k0], W[k0 + 1], h0, l0);
        split2(W[k0 + 8], W[k0 + 9], h1, l1);
        g_wv_p[idx] = make_uint2(h0, h1);
    }
    {
        const float* W = wf1 + n * 128;
        uint4 P;
        split2(W[k0], W[k0 + 1], P.x, P.z);
        split2(W[k0 + 8], W[k0 + 9], P.y, P.w);
        g_wf1_p[idx] = P;
    }
    if (nt < 8) {
        const float* W = wf2 + n * 128;
        uint4 P;
        split2(W[k0], W[k0 + 1], P.x, P.z);
        split2(W[k0 + 8], W[k0 + 9], P.y, P.w);
        g_wf2_p[idx] = P;
    }
}

// ---------------------------------------------------------------------------
// Fused kernel v11: R13 term structure (value 1-term, hmid/flow 3-term fp16x3)
// + cp.async staging of each tile's u lower half (convert phase latency cut)
// + BV hi-only (32KB). 256 threads (8 warps, 4m x 2n), grid 1024, 2 pairs/CTA.
// ---------------------------------------------------------------------------
__global__ __launch_bounds__(256, 1) void fused_gemm(const float* __restrict__ u,
                                                     const float* __restrict__ bf1,
                                                     const float* __restrict__ bf2,
                                                     const float* __restrict__ bv) {
    extern __shared__ char smem[];
    const int t    = threadIdx.x;
    const int wid  = t >> 5;
    const int lane = t & 31;
    const int wm   = wid & 3;   // m group (rows 32*wm)
    const int wn   = wid >> 2;  // n group

    // stage + prefetch first tile while the B copy runs
    {
        const int base0 = blockIdx.x * 256;
        const int b0    = base0 / HWSZ;
        const float* uB0 = u + (size_t)b0 * CINC * HWSZ + (base0 - b0 * HWSZ);
        stage_issue(uB0, smem, t);
        prefetch_hi(uB0, t);
    }

    if (t < 128) ((float*)(smem + SM_BIASF1))[t] = bf1[t];
    if (t < 64)  ((float*)(smem + SM_BIASF2))[t] = bf2[t];
    if (t < 128) ((float*)(smem + SM_BIASV))[t]  = bv[t];

    // ---- 0. copy packed weight fragments to smem ONCE per CTA ----
    {
        uint4* dv = (uint4*)(smem + SM_BV);
        uint4* df = (uint4*)(smem + SM_BF1);
        uint4* d2 = (uint4*)(smem + SM_WF2);
        const uint4* sv = (const uint4*)g_wv_p;
#pragma unroll
        for (int i = t; i < 4096; i += 256) { df[i] = g_wf1_p[i]; }
#pragma unroll
        for (int i = t; i < 2048; i += 256) { dv[i] = sv[i]; d2[i] = g_wf2_p[i]; }
    }

    const float* bf1s = (const float*)(smem + SM_BIASF1);
    const float* bf2s = (const float*)(smem + SM_BIASF2);
    const float* bvs  = (const float*)(smem + SM_BIASV);
    const float* stg  = (const float*)(smem + SM_STAGE);

    for (int pair = blockIdx.x; pair < NPAIRS; pair += GRID_FUSED) {
        const int base0 = pair * 256;
        const int b     = base0 / HWSZ;       // same b for both tiles
        const float* uBb = u + (size_t)b * CINC * HWSZ;

        for (int sub = 0; sub < 2; ++sub) {
            const int m0  = base0 + sub * 128;
            const int hw0 = m0 - b * HWSZ;
            const float* uB = uBb + hw0;

            asm volatile("cp.async.wait_group 0;" ::: "memory");
            __syncthreads();  // stage visible + prior GEMM2 A-reads complete

            // ---- 1. convert A tile -> hi/lo fragments ----
            // warps 0..3: k<64 from smem stage; warps 4..7: k>=64 from gmem(L2).
            {
                const int kk = wid * 16 + 2 * (lane & 3);
                uint4* AH = (uint4*)(smem + SM_A_HI);
                uint4* AL = (uint4*)(smem + SM_A_LO);
                if (wid < 4) {
                    const float* s0 = stg + kk * 132;
                    const float* s1 = stg + (kk + 1) * 132;
                    const float* s2 = stg + (kk + 8) * 132;
                    const float* s3 = stg + (kk + 9) * 132;
#pragma unroll
                    for (int mt = 0; mt < 8; ++mt) {
                        const int m = mt * 16 + (lane >> 2);
                        uint4 H, L;
                        split2(s0[m], s1[m], H.x, L.x);
                        split2(s0[m + 8], s1[m + 8], H.y, L.y);
                        split2(s2[m], s3[m], H.z, L.z);
                        split2(s2[m + 8], s3[m + 8], H.w, L.w);
                        const int slot = (mt * 8 + wid) * 32 + lane;
                        AH[slot] = H;
                        AL[slot] = L;
                    }
                } else {
                    const float* p0 = uB + (size_t)kk * HWSZ;
                    const float* p1 = uB + (size_t)(kk + 1) * HWSZ;
                    const float* p2 = uB + (size_t)(kk + 8) * HWSZ;
                    const float* p3 = uB + (size_t)(kk + 9) * HWSZ;
#pragma unroll
                    for (int mt = 0; mt < 8; ++mt) {
                        const int m = mt * 16 + (lane >> 2);
                        uint4 H, L;
                        split2(p0[m], p1[m], H.x, L.x);
                        split2(p0[m + 8], p1[m + 8], H.y, L.y);
                        split2(p2[m], p3[m], H.z, L.z);
                        split2(p2[m + 8], p3[m + 8], H.w, L.w);
                        const int slot = (mt * 8 + wid) * 32 + lane;
                        AH[slot] = H;
                        AL[slot] = L;
                    }
                }
            }
            __syncthreads();

            // stage + prefetch the NEXT tile (overlaps this tile's GEMMs).
            if (sub == 0) {
                stage_issue(uB + 128, smem, t);
                prefetch_hi(uB + 128, t);
            } else {
                const int np = pair + GRID_FUSED;
                if (np < NPAIRS) {
                    const int nb0 = np * 256;
                    const int nb  = nb0 / HWSZ;
                    const float* uBn = u + (size_t)nb * CINC * HWSZ + (nb0 - nb * HWSZ);
                    stage_issue(uBn, smem, t);
                    prefetch_hi(uBn, t);
                }
            }

            // ---- 2. value (1-term) + hmid (3-term) GEMMs fused ----
            float cv[2][8][4];
            float ch[2][8][4];
#pragma unroll
            for (int i = 0; i < 2; ++i)
#pragma unroll
                for (int nt = 0; nt < 8; ++nt)
#pragma unroll
                    for (int r = 0; r < 4; ++r) { cv[i][nt][r] = 0.0f; ch[i][nt][r] = 0.0f; }

            {
                const uint4* AH = (const uint4*)(smem + SM_A_HI);
                const uint4* AL = (const uint4*)(smem + SM_A_LO);
                const uint2* BV = (const uint2*)(smem + SM_BV);
                const uint4* BF = (const uint4*)(smem + SM_BF1);
#pragma unroll
                for (int kt = 0; kt < 8; ++kt) {
                    const uint4 Ah0 = AH[((2 * wm + 0) * 8 + kt) * 32 + lane];
                    const uint4 Ah1 = AH[((2 * wm + 1) * 8 + kt) * 32 + lane];
                    const uint4 Al0 = AL[((2 * wm + 0) * 8 + kt) * 32 + lane];
                    const uint4 Al1 = AL[((2 * wm + 1) * 8 + kt) * 32 + lane];
#pragma unroll
                    for (int nt = 0; nt < 8; ++nt) {
                        const int bslot = ((8 * wn + nt) * 8 + kt) * 32 + lane;
                        const uint2 Bv = BV[bslot];
                        const uint4 Bf = BF[bslot];
                        mma16816(cv[0][nt], Ah0.x, Ah0.y, Ah0.z, Ah0.w, Bv.x, Bv.y);
                        mma16816(cv[1][nt], Ah1.x, Ah1.y, Ah1.z, Ah1.w, Bv.x, Bv.y);
                        mma16816(ch[0][nt], Ah0.x, Ah0.y, Ah0.z, Ah0.w, Bf.x, Bf.y);
                        mma16816(ch[1][nt], Ah1.x, Ah1.y, Ah1.z, Ah1.w, Bf.x, Bf.y);
                        mma16816(ch[0][nt], Ah0.x, Ah0.y, Ah0.z, Ah0.w, Bf.z, Bf.w);
                        mma16816(ch[1][nt], Ah1.x, Ah1.y, Ah1.z, Ah1.w, Bf.z, Bf.w);
                        mma16816(ch[0][nt], Al0.x, Al0.y, Al0.z, Al0.w, Bf.x, Bf.y);
                        mma16816(ch[1][nt], Al1.x, Al1.y, Al1.z, Al1.w, Bf.x, Bf.y);
                    }
                }
            }

            // ---- 3. value epilogue -> g_value_h (f16x2 per 2 channels) ----
            {
#pragma unroll
                for (int i = 0; i < 2; ++i) {
                    const int hwr = hw0 + 32 * wm + 16 * i + (lane >> 2);
#pragma unroll
                    for (int nt = 0; nt < 8; ++nt) {
                        const int n0   = 64 * wn + 8 * nt + 2 * (lane & 3);
                        const int head = n0 >> 2;
                        const int cih  = (n0 & 3) >> 1;
                        const float bb0 = bvs[n0], bb1 = bvs[n0 + 1];
                        const size_t plane = ((size_t)b * HEADS + head) * HWSZ;
                        g_value_h[(plane + hwr) * 2 + cih] =
                            pack_h2(cv[i][nt][0] + bb0, cv[i][nt][1] + bb1);
                        g_value_h[(plane + hwr + 8) * 2 + cih] =
                            pack_h2(cv[i][nt][2] + bb0, cv[i][nt][3] + bb1);
                    }
                }
            }
            __syncthreads();  // all warps done reading A fragments

            // ---- 4. hmid -> relu -> fp16 split -> A2 fragments (reuse A) ----
            {
                uint4* AH = (uint4*)(smem + SM_A_HI);
                uint4* AL = (uint4*)(smem + SM_A_LO);
#pragma unroll
                for (int i = 0; i < 2; ++i) {
                    const int mtg = 2 * wm + i;
#pragma unroll
                    for (int kl = 0; kl < 4; ++kl) {
                        const int ktg = 4 * wn + kl;
                        const int nt0 = 2 * kl, nt1 = nt0 + 1;
                        const int n00 = 64 * wn + 8 * nt0 + 2 * (lane & 3);
                        const int n10 = n00 + 8;
                        const float b00 = bf1s[n00], b01 = bf1s[n00 + 1];
                        const float b10 = bf1s[n10], b11 = bf1s[n10 + 1];
                        uint4 H, L;
                        split2(fmaxf(ch[i][nt0][0] + b00, 0.0f),
                               fmaxf(ch[i][nt0][1] + b01, 0.0f), H.x, L.x);
                        split2(fmaxf(ch[i][nt0][2] + b00, 0.0f),
                               fmaxf(ch[i][nt0][3] + b01, 0.0f), H.y, L.y);
                        split2(fmaxf(ch[i][nt1][0] + b10, 0.0f),
                               fmaxf(ch[i][nt1][1] + b11, 0.0f), H.z, L.z);
                        split2(fmaxf(ch[i][nt1][2] + b10, 0.0f),
                               fmaxf(ch[i][nt1][3] + b11, 0.0f), H.w, L.w);
                        const int slot = (mtg * 8 + ktg) * 32 + lane;
                        AH[slot] = H;
                        AL[slot] = L;
                    }
                }
            }
            __syncthreads();

            // ---- 5. flow GEMM (N=64, warp tile 32x32, 3 terms) + epilogue ----
            {
                float cf[2][4][4];
#pragma unroll
                for (int i = 0; i < 2; ++i)
#pragma unroll
                    for (int j = 0; j < 4; ++j)
#pragma unroll
                        for (int r = 0; r < 4; ++r) cf[i][j][r] = 0.0f;

                const uint4* AH = (const uint4*)(smem + SM_A_HI);
                const uint4* AL = (const uint4*)(smem + SM_A_LO);
                const uint4* B2 = (const uint4*)(smem + SM_WF2);
#pragma unroll
                for (int kt = 0; kt < 8; ++kt) {
                    const uint4 Ah0 = AH[((2 * wm + 0) * 8 + kt) * 32 + lane];
                    const uint4 Ah1 = AH[((2 * wm + 1) * 8 + kt) * 32 + lane];
                    const uint4 Al0 = AL[((2 * wm + 0) * 8 + kt) * 32 + lane];
                    const uint4 Al1 = AL[((2 * wm + 1) * 8 + kt) * 32 + lane];
#pragma unroll
                    for (int j = 0; j < 4; ++j) {
                        const uint4 Bb = B2[((4 * wn + j) * 8 + kt) * 32 + lane];
                        mma16816(cf[0][j], Ah0.x, Ah0.y, Ah0.z, Ah0.w, Bb.x, Bb.y);
                        mma16816(cf[1][j], Ah1.x, Ah1.y, Ah1.z, Ah1.w, Bb.x, Bb.y);
                        mma16816(cf[0][j], Ah0.x, Ah0.y, Ah0.z, Ah0.w, Bb.z, Bb.w);
                        mma16816(cf[1][j], Ah1.x, Ah1.y, Ah1.z, Ah1.w, Bb.z, Bb.w);
                        mma16816(cf[0][j], Al0.x, Al0.y, Al0.z, Al0.w, Bb.x, Bb.y);
                        mma16816(cf[1][j], Al1.x, Al1.y, Al1.z, Al1.w, Bb.x, Bb.y);
                    }
                }
#pragma unroll
                for (int i = 0; i < 2; ++i) {
                    const int mr = m0 + 32 * wm + 16 * i + (lane >> 2);
#pragma unroll
                    for (int j = 0; j < 4; ++j) {
                        const int n0 = 32 * wn + 8 * j + 2 * (lane & 3);
                        g_flow[(size_t)n0 * TOT + mr]           = cf[i][j][0] + bf2s[n0];
                        g_flow[(size_t)(n0 + 1) * TOT + mr]     = cf[i][j][1] + bf2s[n0 + 1];
                        g_flow[(size_t)n0 * TOT + mr + 8]       = cf[i][j][2] + bf2s[n0];
                        g_flow[(size_t)(n0 + 1) * TOT + mr + 8] = cf[i][j][3] + bf2s[n0 + 1];
                    }
                }
            }
        }
    }
}

// ---------------------------------------------------------------------------
// Kernel 3: periodic bilinear warp, 2D-tiled for gather locality.
// Value is fp16 (uint2 = 4 halves per pixel-head); interpolation in fp32.
// ---------------------------------------------------------------------------
__global__ __launch_bounds__(256) void sample_kernel(float* __restrict__ out) {
    const int lane = threadIdx.x & 31;
    const int wrp  = threadIdx.x >> 5;         // 0..7
    const int tile = blockIdx.x & 63;          // 64 tiles per plane
    const int bh   = blockIdx.x >> 6;          // b*HEADS + head
    const int head = bh & (HEADS - 1);
    const int b    = bh >> 5;
    const int col  = (tile & 7) * 32 + lane;
    const int row0 = (tile >> 3) * 32 + wrp * 4;

    const uint2* vp = (const uint2*)g_value_h + (size_t)bh * HWSZ;
    const float* fxp = g_flow + (size_t)(head * 2) * TOT + (size_t)b * HWSZ;
    const float* fyp = fxp + TOT;
    float* outp = out + ((size_t)b * COUTC + head * 4) * HWSZ;

#pragma unroll
    for (int r = 0; r < 4; ++r) {
        const int h  = row0 + r;
        const int hw = h * 256 + col;

        const float fx = fxp[hw];
        const float fy = fyp[hw];

        const float gx = -1.0f + (2.0f / 255.0f) * (float)col + fx;
        const float gy = -1.0f + (2.0f / 255.0f) * (float)h + fy;

        const float ax = ((gx + 1.0f) * 256.0f - 1.0f) * 0.5f;
        const float ay = ((gy + 1.0f) * 256.0f - 1.0f) * 0.5f;

        float px = fmodf(ax, 256.0f); if (px < 0.0f) px += 256.0f;
        float py = fmodf(ay, 256.0f); if (py < 0.0f) py += 256.0f;

        const float x0f = floorf(px), y0f = floorf(py);
        const float wx = px - x0f, wy = py - y0f;
        int x0 = (int)x0f; x0 = x0 < 0 ? 0 : (x0 > 255 ? 255 : x0);
        int y0 = (int)y0f; y0 = y0 < 0 ? 0 : (y0 > 255 ? 255 : y0);
        const int x1 = (x0 + 1) & 255;
        const int y1 = (y0 + 1) & 255;

        const uint2 q00 = vp[y0 * 256 + x0];
        const uint2 q01 = vp[y0 * 256 + x1];
        const uint2 q10 = vp[y1 * 256 + x0];
        const uint2 q11 = vp[y1 * 256 + x1];

        const float w00 = (1.0f - wx) * (1.0f - wy);
        const float w01 = wx * (1.0f - wy);
        const float w10 = (1.0f - wx) * wy;
        const float w11 = wx * wy;

        const float2 a00 = __half22float2(*(const __half2*)&q00.x);
        const float2 b00 = __half22float2(*(const __half2*)&q00.y);
        const float2 a01 = __half22float2(*(const __half2*)&q01.x);
        const float2 b01 = __half22float2(*(const __half2*)&q01.y);
        const float2 a10 = __half22float2(*(const __half2*)&q10.x);
        const float2 b10 = __half22float2(*(const __half2*)&q10.y);
        const float2 a11 = __half22float2(*(const __half2*)&q11.x);
        const float2 b11 = __half22float2(*(const __half2*)&q11.y);

        const float o0 = a00.x * w00 + a01.x * w01 + a10.x * w10 + a11.x * w11;
        const float o1 = a00.y * w00 + a01.y * w01 + a10.y * w10 + a11.y * w11;
        const float o2 = b00.x * w00 + b01.x * w01 + b10.x * w10 + b11.x * w11;
        const float o3 = b00.y * w00 + b01.y * w01 + b10.y * w10 + b11.y * w11;

        outp[hw]            = o0;
        outp[HWSZ + hw]     = o1;
        outp[2 * HWSZ + hw] = o2;
        outp[3 * HWSZ + hw] = o3;
    }
}

// ---------------------------------------------------------------------------
extern "C" void kernel_launch(void* const* d_in, const int* in_sizes, int n_in,
                              void* d_out, int out_size) {
    const float* u   = (const float*)d_in[0];
    const float* wf1 = (const float*)d_in[1];
    const float* bf1 = (const float*)d_in[2];
    const float* wf2 = (const float*)d_in[3];
    const float* bf2 = (const float*)d_in[4];
    const float* wv  = (const float*)d_in[5];
    const float* bv  = (const float*)d_in[6];
    float* out = (float*)d_out;

    cudaFuncSetAttribute(fused_gemm, cudaFuncAttributeMaxDynamicSharedMemorySize,
                         FUSED_SMEM);

    split_weights<<<16, 256>>>(wv, wf1, wf2);
    fused_gemm<<<GRID_FUSED, 256, FUSED_SMEM>>>(u, bf1, bf2, bv);

    sample_kernel<<<BQ * HEADS * 64, 256>>>(out);
}